// round 5
// baseline (speedup 1.0000x reference)
#include <cuda_runtime.h>
#include <cstdint>

typedef unsigned long long ull_t;

// ---- packed f32x2 helpers ----
__device__ __forceinline__ void ffma2(ull_t &acc, ull_t a, ull_t b) {
    asm volatile("fma.rn.f32x2 %0, %1, %2, %0;" : "+l"(acc) : "l"(a), "l"(b));
}
__device__ __forceinline__ ull_t ffma2o(ull_t a, ull_t b, ull_t c) {
    ull_t r; asm("fma.rn.f32x2 %0, %1, %2, %3;" : "=l"(r) : "l"(a), "l"(b), "l"(c));
    return r;
}
__device__ __forceinline__ ull_t add2(ull_t a, ull_t b) {
    ull_t r; asm("add.rn.f32x2 %0, %1, %2;" : "=l"(r) : "l"(a), "l"(b)); return r;
}
__device__ __forceinline__ float hsum2(ull_t v) {
    float lo, hi; asm("mov.b64 {%0,%1}, %2;" : "=f"(lo), "=f"(hi) : "l"(v));
    return lo + hi;
}
__device__ __forceinline__ ull_t pack2(float lo, float hi) {
    ull_t r; asm("mov.b64 %0, {%1, %2};" : "=l"(r) : "f"(lo), "f"(hi)); return r;
}
__device__ __forceinline__ ull_t mul2(ull_t a, ull_t b) {
    ull_t r; asm("mul.rn.f32x2 %0, %1, %2;" : "=l"(r) : "l"(a), "l"(b)); return r;
}

// scratch: xp = alpha*(x@W_in^T + b_in + b_hh), B=256, T=2048, H=64
#define XP_CAP (256u * 2048u * 64u)
__device__ float g_xp[XP_CAP];

// =====================================================================
// Pre-pass. Block = 256 thr: lane qp=tid&31 owns channel pair (2qp,2qp+1),
// warp rg=tid>>5 owns 4 rows. x staged DUPLICATED as (v,v) f32x2 pairs so
// the whole dot stays in f32x2 lanes=(chA,chB): no hsum tail, STG.64 result.
// =====================================================================
__global__ void __launch_bounds__(256)
xproj_kernel(const float* __restrict__ x,
             const float* __restrict__ W_in,
             const float* __restrict__ b_in,
             const float* __restrict__ b_hh,
             long long BT)
{
    constexpr int ROWS = 32;
    constexpr int D = 32;
    const float alpha = (float)(16.67 / 40.0);

    __shared__ __align__(16) ull_t xsd[ROWS * D];   // duplicated x: 8KB

    const int tid = threadIdx.x;
    const int qp  = tid & 31;        // channel pair index
    const int rg  = tid >> 5;        // warp / row group
    const long long row0 = (long long)blockIdx.x * ROWS;

    // stage + duplicate: each thread handles 4 floats (one float4)
    {
        const long long lim4 = BT * (D / 4);
        long long u4 = row0 * (D / 4) + tid;
        float4 v = (u4 < lim4) ? reinterpret_cast<const float4*>(x)[u4]
                               : make_float4(0.f, 0.f, 0.f, 0.f);
        ull_t* dst = &xsd[tid * 4];
        dst[0] = pack2(v.x, v.x);
        dst[1] = pack2(v.y, v.y);
        dst[2] = pack2(v.z, v.z);
        dst[3] = pack2(v.w, v.w);
    }
    __syncthreads();

    // weight pairs: wiP[k] = (W_in[2qp][k], W_in[2qp+1][k])
    ull_t wiP[D];
    {
        const float4* ra = reinterpret_cast<const float4*>(W_in + (2 * qp) * D);
        const float4* rb = reinterpret_cast<const float4*>(W_in + (2 * qp + 1) * D);
#pragma unroll
        for (int m = 0; m < D / 4; m++) {
            float4 a = ra[m], bq = rb[m];
            wiP[4 * m + 0] = pack2(a.x, bq.x);
            wiP[4 * m + 1] = pack2(a.y, bq.y);
            wiP[4 * m + 2] = pack2(a.z, bq.z);
            wiP[4 * m + 3] = pack2(a.w, bq.w);
        }
    }
    const ull_t alpha2 = pack2(alpha, alpha);
    const ull_t ab2 = pack2(alpha * (b_in[2 * qp] + b_hh[2 * qp]),
                            alpha * (b_in[2 * qp + 1] + b_hh[2 * qp + 1]));

#pragma unroll
    for (int r = 0; r < 4; r++) {
        const int row = rg * 4 + r;
        const long long grow = row0 + row;
        if (grow >= BT) break;
        const ull_t* xr = &xsd[row * D];
        ull_t a0 = 0ull, a1 = 0ull, a2 = 0ull, a3 = 0ull;
#pragma unroll
        for (int m = 0; m < D / 2; m++) {
            // ulonglong2 load -> 2 FFMA2
            ulonglong2 xv = reinterpret_cast<const ulonglong2*>(xr)[m];
            ffma2((m & 1) ? a1 : a0, wiP[2 * m],     xv.x);
            ffma2((m & 1) ? a3 : a2, wiP[2 * m + 1], xv.y);
        }
        ull_t pre = add2(add2(a0, a1), add2(a2, a3));
        ull_t res = ffma2o(pre, alpha2, ab2);
        reinterpret_cast<ull_t*>(g_xp)[grow * 32 + qp] = res;
    }
}

// =====================================================================
// Recurrence: grid = B, block = 64 = ONE batch per CTA (plain syncthreads,
// bar-0 floor). xp fed by 4-deep LDG register prefetch ring (no smem, no
// chunk barriers). h double-buffered in 512B smem; broadcast LDS.128 reads.
// =====================================================================
__global__ void __launch_bounds__(64)
ctrnn_scan_kernel(const float* __restrict__ W_hh,
                  float* __restrict__ out,
                  int B, int T)
{
    constexpr int H = 64;
    const int j = threadIdx.x;
    const int b = blockIdx.x;

    __shared__ __align__(16) float hbuf[2][H];

    const float alpha = (float)(16.67 / 40.0);
    const float oma   = (float)(1.0 - 16.67 / 40.0);
    const ull_t alpha2 = pack2(alpha, alpha);

    // Wa = alpha * W_hh[j] as packed pairs
    ull_t wu[32];
    {
        const ulonglong2* wr = reinterpret_cast<const ulonglong2*>(W_hh + j * H);
#pragma unroll
        for (int m = 0; m < 16; m++) {
            ulonglong2 v = wr[m];
            wu[2 * m]     = mul2(v.x, alpha2);
            wu[2 * m + 1] = mul2(v.y, alpha2);
        }
    }

    const float* __restrict__ xpb = g_xp + ((size_t)b * T) * H + j;

    // prefetch ring, depth 4
    float xpr[4];
#pragma unroll
    for (int q = 0; q < 4; q++) {
        int idx = q < T ? q : (T - 1);
        xpr[q] = __ldg(xpb + (size_t)idx * H);
    }

    hbuf[0][j] = 0.0f;
    float hj = 0.0f;
    __syncthreads();

    float* __restrict__ outb = out + (size_t)b * T * H + j;

    int cur = 0;
#pragma unroll 4
    for (int t = 0; t < T; t++) {
        const ulonglong2* hp = reinterpret_cast<const ulonglong2*>(hbuf[cur]);
        ull_t a0 = pack2(xpr[t & 3], 0.0f);
        ull_t a1 = 0ull, a2 = 0ull, a3 = 0ull;
#pragma unroll
        for (int m = 0; m < 16; m++) {
            ulonglong2 hv = hp[m];
            ffma2((m & 1) ? a1 : a0, wu[2 * m],     hv.x);
            ffma2((m & 1) ? a3 : a2, wu[2 * m + 1], hv.y);
        }
        float pre  = hsum2(add2(add2(a0, a1), add2(a2, a3)));
        float hnew = fmaxf(fmaf(hj, oma, pre), 0.0f);
        hbuf[cur ^ 1][j] = hnew;
        outb[(size_t)t * H] = hnew;
        // refill ring slot for t+4 (clamped; extra read harmless)
        int nidx = t + 4 < T ? t + 4 : (T - 1);
        xpr[t & 3] = __ldg(xpb + (size_t)nidx * H);
        hj = hnew;
        cur ^= 1;
        __syncthreads();
    }

    // h_last appended after outputs
    out[(size_t)B * T * H + (size_t)b * H + j] = hj;
}

extern "C" void kernel_launch(void* const* d_in, const int* in_sizes, int n_in,
                              void* d_out, int out_size)
{
    const float* x    = (const float*)d_in[0];
    // d_in[1] = seq_lengths: forward-dead (mask only gates gradients)
    const float* W_in = (const float*)d_in[2];
    const float* b_in = (const float*)d_in[3];
    const float* W_hh = (const float*)d_in[4];
    const float* b_hh = (const float*)d_in[5];
    float* out = (float*)d_out;

    const int B = in_sizes[1];
    const int H = in_sizes[5];
    const int D = in_sizes[2] / H;
    const long long T = (long long)in_sizes[0] / ((long long)B * D);
    const long long BT = (long long)B * T;

    // pre-pass: xp = alpha*(x@W_in^T + b_in + b_hh)
    const int pgrid = (int)((BT + 31) / 32);
    xproj_kernel<<<pgrid, 256>>>(x, W_in, b_in, b_hh, BT);

    // recurrence: one batch per CTA
    ctrnn_scan_kernel<<<B, 64>>>(W_hh, out, B, (int)T);
}

// round 6
// speedup vs baseline: 1.9367x; 1.9367x over previous
#include <cuda_runtime.h>
#include <cstdint>

typedef unsigned long long ull_t;

// ---- packed f32x2 helpers ----
__device__ __forceinline__ void ffma2(ull_t &acc, ull_t a, ull_t b) {
    asm volatile("fma.rn.f32x2 %0, %1, %2, %0;" : "+l"(acc) : "l"(a), "l"(b));
}
__device__ __forceinline__ ull_t ffma2o(ull_t a, ull_t b, ull_t c) {
    ull_t r; asm("fma.rn.f32x2 %0, %1, %2, %3;" : "=l"(r) : "l"(a), "l"(b), "l"(c));
    return r;
}
__device__ __forceinline__ ull_t add2(ull_t a, ull_t b) {
    ull_t r; asm("add.rn.f32x2 %0, %1, %2;" : "=l"(r) : "l"(a), "l"(b)); return r;
}
__device__ __forceinline__ float hsum2(ull_t v) {
    float lo, hi; asm("mov.b64 {%0,%1}, %2;" : "=f"(lo), "=f"(hi) : "l"(v));
    return lo + hi;
}
__device__ __forceinline__ ull_t pack2(float lo, float hi) {
    ull_t r; asm("mov.b64 %0, {%1, %2};" : "=l"(r) : "f"(lo), "f"(hi)); return r;
}
__device__ __forceinline__ ull_t mul2(ull_t a, ull_t b) {
    ull_t r; asm("mul.rn.f32x2 %0, %1, %2;" : "=l"(r) : "l"(a), "l"(b)); return r;
}

__device__ __forceinline__ void cp_async16(uint32_t dst, const void* src, int src_sz) {
    asm volatile("cp.async.cg.shared.global [%0], [%1], 16, %2;"
                 :: "r"(dst), "l"(src), "r"(src_sz));
}
__device__ __forceinline__ void cp_commit() {
    asm volatile("cp.async.commit_group;");
}
__device__ __forceinline__ void cp_wait1() {
    asm volatile("cp.async.wait_group 1;" ::: "memory");
}

// scratch: xp = alpha*(x@W_in^T + b_in + b_hh), B=256, T=2048, H=64
#define XP_CAP (256u * 2048u * 64u)
__device__ float g_xp[XP_CAP];

// =====================================================================
// Pre-pass. Block = 256 thr, 128 rows. Lane qp=tid&31 owns channel pair
// (2qp, 2qp+1); group rg=tid>>5 owns 16 rows. x staged DUPLICATED as (v,v)
// f32x2 so the whole dot stays packed: no hsum tail, STG.64 result.
// Weight setup (32 ull regs) amortized over 16 rows/thread.
// =====================================================================
__global__ void __launch_bounds__(256)
xproj_kernel(const float* __restrict__ x,
             const float* __restrict__ W_in,
             const float* __restrict__ b_in,
             const float* __restrict__ b_hh,
             long long BT)
{
    constexpr int ROWS = 128;
    constexpr int D = 32;
    const float alpha = (float)(16.67 / 40.0);

    __shared__ __align__(16) ull_t xsd[ROWS * D];   // duplicated x: 32KB

    const int tid = threadIdx.x;
    const int qp  = tid & 31;        // channel pair index
    const int rg  = tid >> 5;        // row group (8 groups x 16 rows)
    const long long row0 = (long long)blockIdx.x * ROWS;

    // stage + duplicate: 1024 float4 units, 4 per thread
    {
        const long long lim4 = BT * (D / 4);
#pragma unroll
        for (int q = 0; q < 4; q++) {
            int u = tid + 256 * q;
            long long u4 = row0 * (D / 4) + u;
            float4 v = (u4 < lim4) ? reinterpret_cast<const float4*>(x)[u4]
                                   : make_float4(0.f, 0.f, 0.f, 0.f);
            ull_t* dst = &xsd[u * 4];
            dst[0] = pack2(v.x, v.x);
            dst[1] = pack2(v.y, v.y);
            dst[2] = pack2(v.z, v.z);
            dst[3] = pack2(v.w, v.w);
        }
    }
    __syncthreads();

    // weight pairs: wiP[k] = (W_in[2qp][k], W_in[2qp+1][k])
    ull_t wiP[D];
    {
        const float4* ra = reinterpret_cast<const float4*>(W_in + (2 * qp) * D);
        const float4* rb = reinterpret_cast<const float4*>(W_in + (2 * qp + 1) * D);
#pragma unroll
        for (int m = 0; m < D / 4; m++) {
            float4 a = ra[m], bq = rb[m];
            wiP[4 * m + 0] = pack2(a.x, bq.x);
            wiP[4 * m + 1] = pack2(a.y, bq.y);
            wiP[4 * m + 2] = pack2(a.z, bq.z);
            wiP[4 * m + 3] = pack2(a.w, bq.w);
        }
    }
    const ull_t alpha2 = pack2(alpha, alpha);
    const ull_t ab2 = pack2(alpha * (b_in[2 * qp] + b_hh[2 * qp]),
                            alpha * (b_in[2 * qp + 1] + b_hh[2 * qp + 1]));

#pragma unroll 4
    for (int r = 0; r < 16; r++) {
        const int row = rg * 16 + r;
        const long long grow = row0 + row;
        if (grow >= BT) break;
        const ulonglong2* xr = reinterpret_cast<const ulonglong2*>(&xsd[row * D]);
        ull_t a0 = 0ull, a1 = 0ull, a2 = 0ull, a3 = 0ull;
#pragma unroll
        for (int m = 0; m < D / 2; m++) {
            ulonglong2 xv = xr[m];
            ffma2((m & 1) ? a1 : a0, wiP[2 * m],     xv.x);
            ffma2((m & 1) ? a3 : a2, wiP[2 * m + 1], xv.y);
        }
        ull_t pre = add2(add2(a0, a1), add2(a2, a3));
        reinterpret_cast<ull_t*>(g_xp)[grow * 32 + qp] = ffma2o(pre, alpha2, ab2);
    }
}

// =====================================================================
// Recurrence (R4 structure, bar0 instead of named bars):
// Block = 128 thr = 2 batches (warps 0-1 = batch0, warps 2-3 = batch1,
// covering all 4 SMSPs). Thread = one channel j. __syncthreads per step
// (bar0 floor 7cyc vs named-bar ~47). xp staged in CH-step cp.async chunks.
// =====================================================================
__global__ void __launch_bounds__(128, 1)
ctrnn_scan_kernel(const float* __restrict__ W_hh,
                  float* __restrict__ out,
                  int B, int T)
{
    constexpr int H  = 64;
    constexpr int CH = 32;   // timesteps per xp-staging chunk

    const int tid = threadIdx.x;
    const int sb  = tid >> 6;        // batch slot (0/1)
    const int j   = tid & 63;        // channel
    const int b   = blockIdx.x * 2 + sb;
    const bool active = (b < B);
    const int bc  = active ? b : (B - 1);

    __shared__ __align__(16) float hbuf[2][2][H];           // [ping][sb][H]
    __shared__ __align__(16) float xbuf[2][2][CH * H];      // [ping][sb][CH*H] (32KB)

    const float alpha = (float)(16.67 / 40.0);
    const float oma   = (float)(1.0 - 16.67 / 40.0);
    const ull_t alpha2 = pack2(alpha, alpha);

    // Wa = alpha * W_hh[j] packed
    ull_t wu[32];
    {
        const ulonglong2* wr = reinterpret_cast<const ulonglong2*>(W_hh + j * H);
#pragma unroll
        for (int m = 0; m < 16; m++) {
            ulonglong2 v = wr[m];
            wu[2 * m]     = mul2(v.x, alpha2);
            wu[2 * m + 1] = mul2(v.y, alpha2);
        }
    }

    hbuf[0][sb][j] = 0.0f;
    float hj = 0.0f;

    const int nchunk = (T + CH - 1) / CH;

    // xp chunk loader: CH*H*4 = 8KB = 512 x 16B units; 64 thr -> 8 each
    auto issue_chunk = [&](int c, int buf) {
        const float* src = g_xp + ((size_t)bc * T + (size_t)c * CH) * H;
        const char* srcb = (const char*)src;
        uint32_t dstb = (uint32_t)__cvta_generic_to_shared(&xbuf[buf][sb][0]);
#pragma unroll
        for (int q = 0; q < 8; q++) {
            int off16 = j + 64 * q;          // 512 units per chunk
            int row   = off16 >> 4;          // 16 units (256B) per timestep
            bool ok   = active && (c * CH + row) < T;
            const void* s = ok ? (const void*)(srcb + (size_t)off16 * 16)
                               : (const void*)g_xp;
            cp_async16(dstb + off16 * 16, s, ok ? 16 : 0);
        }
        cp_commit();
    };

    issue_chunk(0, 0);
    if (nchunk > 1) issue_chunk(1, 1); else cp_commit();

    int cur = 0;
    const size_t outbase = (size_t)bc * T * H + j;

#define STEP_BODY(tt)                                                              \
    {                                                                              \
        const ulonglong2* hp = reinterpret_cast<const ulonglong2*>(hbuf[cur][sb]); \
        const float xps = xbuf[xb][sb][(tt) * H + j];                              \
        ull_t a0 = pack2(xps, 0.0f);                                               \
        ull_t a1 = 0ull, a2 = 0ull, a3 = 0ull;                                     \
        _Pragma("unroll")                                                          \
        for (int m = 0; m < 16; m++) {                                             \
            ulonglong2 hv = hp[m];                                                 \
            ffma2((m & 1) ? a1 : a0, wu[2 * m],     hv.x);                         \
            ffma2((m & 1) ? a3 : a2, wu[2 * m + 1], hv.y);                         \
        }                                                                          \
        float p = hsum2(add2(add2(a0, a1), add2(a2, a3)));                         \
        float hnew = fmaxf(fmaf(hj, oma, p), 0.0f);                                \
        hbuf[cur ^ 1][sb][j] = hnew;                                               \
        if (active) out[obase_c + (size_t)(tt) * H] = hnew;                        \
        hj = hnew;                                                                 \
        cur ^= 1;                                                                  \
        __syncthreads();                                                           \
    }

    for (int c = 0; c < nchunk; c++) {
        cp_wait1();            // this thread's chunk-c copies landed
        __syncthreads();       // CTA-wide visibility of xbuf chunk c (+ hbuf)

        const int xb   = c & 1;
        const int tend = min(CH, T - c * CH);
        const size_t obase_c = outbase + (size_t)c * CH * H;

        if (tend == CH) {
#pragma unroll 4
            for (int tt = 0; tt < CH; tt++) STEP_BODY(tt)
        } else {
            for (int tt = 0; tt < tend; tt++) STEP_BODY(tt)
        }

        if (c + 2 < nchunk) issue_chunk(c + 2, xb); else cp_commit();
    }
#undef STEP_BODY

    // h_last appended after outputs
    if (active) out[(size_t)B * T * H + (size_t)b * H + j] = hj;
}

extern "C" void kernel_launch(void* const* d_in, const int* in_sizes, int n_in,
                              void* d_out, int out_size)
{
    const float* x    = (const float*)d_in[0];
    // d_in[1] = seq_lengths: forward-dead (mask only gates gradients)
    const float* W_in = (const float*)d_in[2];
    const float* b_in = (const float*)d_in[3];
    const float* W_hh = (const float*)d_in[4];
    const float* b_hh = (const float*)d_in[5];
    float* out = (float*)d_out;

    const int B = in_sizes[1];
    const int H = in_sizes[5];
    const int D = in_sizes[2] / H;
    const long long T = (long long)in_sizes[0] / ((long long)B * D);
    const long long BT = (long long)B * T;

    // pre-pass: xp = alpha*(x@W_in^T + b_in + b_hh)
    const int pgrid = (int)((BT + 127) / 128);
    xproj_kernel<<<pgrid, 256>>>(x, W_in, b_in, b_hh, BT);

    // recurrence: 2 batches per CTA
    const int grid = (B + 1) / 2;
    ctrnn_scan_kernel<<<grid, 128>>>(W_hh, out, B, (int)T);
}

// round 7
// speedup vs baseline: 2.2467x; 1.1600x over previous
#include <cuda_runtime.h>
#include <cstdint>

typedef unsigned long long ull_t;

// ---- packed f32x2 helpers ----
__device__ __forceinline__ void ffma2(ull_t &acc, ull_t a, ull_t b) {
    asm volatile("fma.rn.f32x2 %0, %1, %2, %0;" : "+l"(acc) : "l"(a), "l"(b));
}
__device__ __forceinline__ ull_t add2(ull_t a, ull_t b) {
    ull_t r; asm("add.rn.f32x2 %0, %1, %2;" : "=l"(r) : "l"(a), "l"(b)); return r;
}
__device__ __forceinline__ float hsum2(ull_t v) {
    float lo, hi; asm("mov.b64 {%0,%1}, %2;" : "=f"(lo), "=f"(hi) : "l"(v));
    return lo + hi;
}
__device__ __forceinline__ ull_t pack2(float lo, float hi) {
    ull_t r; asm("mov.b64 %0, {%1, %2};" : "=l"(r) : "f"(lo), "f"(hi)); return r;
}
__device__ __forceinline__ ull_t mul2(ull_t a, ull_t b) {
    ull_t r; asm("mul.rn.f32x2 %0, %1, %2;" : "=l"(r) : "l"(a), "l"(b)); return r;
}

__device__ __forceinline__ void cp_async16(uint32_t dst, const void* src, int src_sz) {
    asm volatile("cp.async.cg.shared.global [%0], [%1], 16, %2;"
                 :: "r"(dst), "l"(src), "r"(src_sz));
}
__device__ __forceinline__ void cp_commit() {
    asm volatile("cp.async.commit_group;");
}
__device__ __forceinline__ void cp_wait1() {
    asm volatile("cp.async.wait_group 1;" ::: "memory");
}
// per-batch barrier over 64 threads (2 warps) — measured faster than bar0-128
__device__ __forceinline__ void group_bar(int id) {
    asm volatile("bar.sync %0, 64;" :: "r"(id) : "memory");
}

// scratch for precomputed alpha*(x@W_in^T + b_in + b_hh): B=256, T=2048, H=64
#define XP_CAP (256u * 2048u * 64u)
__device__ float g_xp[XP_CAP];

// =====================================================================
// Pre-pass: xp[row, j] = alpha * (x[row,:]·W_in[j,:] + b_in[j] + b_hh[j])
// row = b*T + t; block = 256 thr handles 128 rows; thread = (j, rowgroup).
// NO min-blocks clamp (R4's ",4" forced 64 regs -> spills).
// =====================================================================
__global__ void __launch_bounds__(256)
xproj_kernel(const float* __restrict__ x,
             const float* __restrict__ W_in,
             const float* __restrict__ b_in,
             const float* __restrict__ b_hh,
             long long BT)
{
    constexpr int ROWS = 128;
    constexpr int D = 32;
    const float alpha = (float)(16.67 / 40.0);

    __shared__ __align__(16) float xs[ROWS * D];   // 16KB

    const int tid = threadIdx.x;
    const int j   = tid & 63;
    const int rg  = tid >> 6;
    const long long row0 = (long long)blockIdx.x * ROWS;

    // stage x tile: 128 rows * 32 f = 1024 x 16B units; 4 per thread
    {
        const float4* src = reinterpret_cast<const float4*>(x) + row0 * (D / 4);
        float4* dst = reinterpret_cast<float4*>(xs);
        const long long lim = BT * (D / 4) - row0 * (D / 4);
#pragma unroll
        for (int q = 0; q < 4; q++) {
            int u = tid + 256 * q;
            float4 v = (u < lim) ? src[u] : make_float4(0.f, 0.f, 0.f, 0.f);
            dst[u] = v;
        }
    }
    __syncthreads();

    // W_in row j in packed registers
    ull_t wi[16];
    {
        const ulonglong2* wr = reinterpret_cast<const ulonglong2*>(W_in + j * D);
#pragma unroll
        for (int m = 0; m < 8; m++) { ulonglong2 v = wr[m]; wi[2*m] = v.x; wi[2*m+1] = v.y; }
    }
    const float ab = alpha * (b_in[j] + b_hh[j]);

#pragma unroll 8
    for (int rr = 0; rr < 32; rr++) {
        const int r = rg * 32 + rr;
        const long long row = row0 + r;
        if (row >= BT) break;
        const ulonglong2* xr = reinterpret_cast<const ulonglong2*>(&xs[r * D]);
        ull_t a0 = 0ull, a1 = 0ull, a2 = 0ull, a3 = 0ull;
#pragma unroll
        for (int m = 0; m < 8; m++) {
            ulonglong2 v = xr[m];
            ffma2((m & 1) ? a1 : a0, wi[2 * m],     v.x);
            ffma2((m & 1) ? a3 : a2, wi[2 * m + 1], v.y);
        }
        float dot = hsum2(add2(add2(a0, a1), add2(a2, a3)));
        g_xp[row * 64 + j] = fmaf(dot, alpha, ab);
    }
}

// =====================================================================
// Recurrence (R4 proven config): h <- relu(oma*h + Wa·h + xp).
// Block = 128 thr = 2 independent batches (64 thr each, own named barrier,
// warps 0-1 = batch0 on SMSP0-1, warps 2-3 = batch1 on SMSP2-3).
// Thread = one channel j. xp staged in CH-step chunks via cp.async.
// =====================================================================
__global__ void __launch_bounds__(128, 1)
ctrnn_scan_kernel(const float* __restrict__ W_hh,
                  float* __restrict__ out,
                  int B, int T)
{
    constexpr int H  = 64;
    constexpr int CH = 32;   // timesteps per xp-staging chunk

    const int tid = threadIdx.x;
    const int sb  = tid >> 6;        // batch slot (0/1)
    const int j   = tid & 63;        // channel
    const int barid = sb + 1;
    const int b   = blockIdx.x * 2 + sb;
    const bool active = (b < B);
    const int bc  = active ? b : (B - 1);

    __shared__ __align__(16) float hbuf[2][2][H];           // [ping][sb][H]
    __shared__ __align__(16) float xbuf[2][2][CH * H];      // [ping][sb][CH*H] (32KB)

    const float alpha = (float)(16.67 / 40.0);
    const float oma   = (float)(1.0 - 16.67 / 40.0);
    const ull_t alpha2 = pack2(alpha, alpha);

    // Wa = alpha * W_hh[j] packed
    ull_t wu[32];
    {
        const ulonglong2* wr = reinterpret_cast<const ulonglong2*>(W_hh + j * H);
#pragma unroll
        for (int m = 0; m < 16; m++) {
            ulonglong2 v = wr[m];
            wu[2 * m]     = mul2(v.x, alpha2);
            wu[2 * m + 1] = mul2(v.y, alpha2);
        }
    }

    hbuf[0][sb][j] = 0.0f;
    float hj = 0.0f;

    const int nchunk = (T + CH - 1) / CH;

    // xp chunk loader: CH*H*4 = 8KB = 512 x 16B units; 64 thr -> 8 each
    auto issue_chunk = [&](int c, int buf) {
        const float* src = g_xp + ((size_t)bc * T + (size_t)c * CH) * H;
        const char* srcb = (const char*)src;
        uint32_t dstb = (uint32_t)__cvta_generic_to_shared(&xbuf[buf][sb][0]);
#pragma unroll
        for (int q = 0; q < 8; q++) {
            int off16 = j + 64 * q;          // 512 units per chunk
            int row   = off16 >> 4;          // 16 units (256B) per timestep
            bool ok   = active && (c * CH + row) < T;
            const void* s = ok ? (const void*)(srcb + (size_t)off16 * 16)
                               : (const void*)g_xp;
            cp_async16(dstb + off16 * 16, s, ok ? 16 : 0);
        }
        cp_commit();
    };

    issue_chunk(0, 0);
    if (nchunk > 1) issue_chunk(1, 1); else cp_commit();

    int cur = 0;
    const size_t outbase = (size_t)bc * T * H + j;

#define STEP_BODY(tt)                                                              \
    {                                                                              \
        const ulonglong2* hp = reinterpret_cast<const ulonglong2*>(hbuf[cur][sb]); \
        const float xps = xbuf[xb][sb][(tt) * H + j];                              \
        ull_t a0 = pack2(xps, 0.0f);                                               \
        ull_t a1 = 0ull, a2 = 0ull, a3 = 0ull;                                     \
        _Pragma("unroll")                                                          \
        for (int m = 0; m < 16; m++) {                                             \
            ulonglong2 hv = hp[m];                                                 \
            ffma2((m & 1) ? a1 : a0, wu[2 * m],     hv.x);                         \
            ffma2((m & 1) ? a3 : a2, wu[2 * m + 1], hv.y);                         \
        }                                                                          \
        float p = hsum2(add2(add2(a0, a1), add2(a2, a3)));                         \
        float hnew = fmaxf(fmaf(hj, oma, p), 0.0f);                                \
        hbuf[cur ^ 1][sb][j] = hnew;                                               \
        if (active) out[obase_c + (size_t)(tt) * H] = hnew;                        \
        hj = hnew;                                                                 \
        cur ^= 1;                                                                  \
        group_bar(barid);                                                          \
    }

    for (int c = 0; c < nchunk; c++) {
        cp_wait1();            // this thread's chunk-c copies landed
        group_bar(barid);      // batch-wide visibility of xbuf chunk c (+ hbuf)

        const int xb   = c & 1;
        const int tend = min(CH, T - c * CH);
        const size_t obase_c = outbase + (size_t)c * CH * H;

        if (tend == CH) {
#pragma unroll 4
            for (int tt = 0; tt < CH; tt++) STEP_BODY(tt)
        } else {
            for (int tt = 0; tt < tend; tt++) STEP_BODY(tt)
        }

        if (c + 2 < nchunk) issue_chunk(c + 2, xb); else cp_commit();
    }
#undef STEP_BODY

    // h_last appended after outputs
    if (active) out[(size_t)B * T * H + (size_t)b * H + j] = hj;
}

extern "C" void kernel_launch(void* const* d_in, const int* in_sizes, int n_in,
                              void* d_out, int out_size)
{
    const float* x    = (const float*)d_in[0];
    // d_in[1] = seq_lengths: forward-dead (mask only gates gradients)
    const float* W_in = (const float*)d_in[2];
    const float* b_in = (const float*)d_in[3];
    const float* W_hh = (const float*)d_in[4];
    const float* b_hh = (const float*)d_in[5];
    float* out = (float*)d_out;

    const int B = in_sizes[1];
    const int H = in_sizes[5];
    const int D = in_sizes[2] / H;
    const long long T = (long long)in_sizes[0] / ((long long)B * D);
    const long long BT = (long long)B * T;

    // pre-pass: xp = alpha*(x@W_in^T + b_in + b_hh)
    const int pgrid = (int)((BT + 127) / 128);
    xproj_kernel<<<pgrid, 256>>>(x, W_in, b_in, b_hh, BT);

    // recurrence: 2 batches per CTA
    const int grid = (B + 1) / 2;
    ctrnn_scan_kernel<<<grid, 128>>>(W_hh, out, B, (int)T);
}